// round 16
// baseline (speedup 1.0000x reference)
#include <cuda_runtime.h>
#include <cuda_fp16.h>
#include <math.h>
#include <stdint.h>

#define THREADS 256
#define GRID    4096
#define NSAMP   64

// ---------------- weight fragment image (fp16, mma-fragment order, K zero-padded) ----------------
#define IOFF_L0   0u
#define IOFF_L1   16384u
#define IOFF_L2   81920u
#define IOFF_L3   147456u
#define IOFF_L4   212992u
#define IOFF_L5   294912u
#define IOFF_L6   360448u
#define IOFF_L7   425984u
#define IOFF_FT   491520u
#define IOFF_DIR  557056u
#define IMG_ELEMS 598016u

// uint4 per (chunk32, n8tile, lane): {b0,b1 of k16-step0, b0,b1 of k16-step1}
__device__ __align__(16) uint4 g_wf[IMG_ELEMS / 8];

// ---------------- smem layout (bytes) ----------------
#define SM_ACT   0        // [64][264] fp16 activations (stride 528B, ldsm conflict-free)
#define SM_EMB   33792    // [64][72] fp16 emb (xyz, later dir; stride 72)
#define SM_DENSP 43008    // 4x64 f32 density partials (per n-group)
#define SM_RGBP  44032    // 12x64 f32 rgb partials (ch*4+wn)
#define SM_DENS  47104    // 64 f32
#define SM_DIRS  47360    // 32 f32
#define SMEM_BYTES 47616  // x2 CTAs ~ 95KB

// ---------------- low-level helpers ----------------
__device__ __forceinline__ uint32_t s2u(const void* p) {
    uint32_t a;
    asm("{ .reg .u64 t; cvta.to.shared.u64 t, %1; cvt.u32.u64 %0, t; }" : "=r"(a) : "l"(p));
    return a;
}
__device__ __forceinline__ void ldsm4(uint32_t* r, uint32_t a) {
    asm volatile("ldmatrix.sync.aligned.m8n8.x4.shared.b16 {%0,%1,%2,%3}, [%4];"
        : "=r"(r[0]), "=r"(r[1]), "=r"(r[2]), "=r"(r[3]) : "r"(a));
}
__device__ __forceinline__ void mma_f16(float* c, const uint32_t* a, const uint32_t* b) {
    asm volatile("mma.sync.aligned.m16n8k16.row.col.f32.f16.f16.f32 "
        "{%0,%1,%2,%3},{%4,%5,%6,%7},{%8,%9},{%0,%1,%2,%3};"
        : "+f"(c[0]), "+f"(c[1]), "+f"(c[2]), "+f"(c[3])
        : "r"(a[0]), "r"(a[1]), "r"(a[2]), "r"(a[3]), "r"(b[0]), "r"(b[1]));
}
__device__ __forceinline__ uint32_t packh(float x, float y) {
    __half2 h = __floats2half2_rn(x, y);
    return *reinterpret_cast<uint32_t*>(&h);
}

// ---------------- weight prep: fp32 -> fp16 fragments, one launch ----------------
// Fragment layout per layer (NT = N/8 n8-tiles): uint4 index = (chunk*NT + n8)*32 + lane.
// q-th u32 of the uint4 = b-reg: q0 -> (k16=0, b0), q1 -> (k16=0, b1=k+8), q2/q3 -> k16=1.
// Thread fragment element: n = n8*8 + lane/4, k = chunk*32 + (q>>1)*16 + (q&1)*8 + (lane&3)*2.
__global__ void prep_all(const float* __restrict__ W0, const float* __restrict__ W1,
                         const float* __restrict__ W2, const float* __restrict__ W3,
                         const float* __restrict__ W4, const float* __restrict__ W5,
                         const float* __restrict__ W6, const float* __restrict__ W7,
                         const float* __restrict__ W8, const float* __restrict__ W9) {
    unsigned idx = blockIdx.x * blockDim.x + threadIdx.x;   // u32 index
    if (idx >= IMG_ELEMS / 2) return;
    unsigned e = idx * 2;
    unsigned off; const float* W; int ind, Nrows;
    if      (e < IOFF_L1)  { off = IOFF_L0;  W = W0; ind = 63;  Nrows = 256; }
    else if (e < IOFF_L2)  { off = IOFF_L1;  W = W1; ind = 256; Nrows = 256; }
    else if (e < IOFF_L3)  { off = IOFF_L2;  W = W2; ind = 256; Nrows = 256; }
    else if (e < IOFF_L4)  { off = IOFF_L3;  W = W3; ind = 256; Nrows = 256; }
    else if (e < IOFF_L5)  { off = IOFF_L4;  W = W4; ind = 319; Nrows = 256; }
    else if (e < IOFF_L6)  { off = IOFF_L5;  W = W5; ind = 256; Nrows = 256; }
    else if (e < IOFF_L7)  { off = IOFF_L6;  W = W6; ind = 256; Nrows = 256; }
    else if (e < IOFF_FT)  { off = IOFF_L7;  W = W7; ind = 256; Nrows = 256; }
    else if (e < IOFF_DIR) { off = IOFF_FT;  W = W8; ind = 256; Nrows = 256; }
    else                   { off = IOFF_DIR; W = W9; ind = 283; Nrows = 128; }
    unsigned r = idx - off / 2;
    int NT = Nrows >> 3;
    unsigned f = r >> 2, q = r & 3;
    unsigned per = (unsigned)NT * 32u;
    int chunk = f / per;
    int rem = f - chunk * per;
    int n8 = rem >> 5, ln = rem & 31;
    int n = n8 * 8 + (ln >> 2);
    int k0 = chunk * 32 + ((q >> 1) << 4) + ((q & 1) << 3) + ((ln & 3) << 1);
    float w0 = (k0     < ind) ? __ldg(W + (size_t)n * ind + k0)     : 0.0f;
    float w1 = (k0 + 1 < ind) ? __ldg(W + (size_t)n * ind + k0 + 1) : 0.0f;
    reinterpret_cast<uint32_t*>(g_wf)[idx] = packh(w0, w1);
}

// ---------------- one layer ----------------
// 8 warps: wm = w&1 -> 32 m-rows; wn = w>>1 -> NB n8-tiles (NB*8 n cols). N = NB*32.
// B fragments straight from L2 via LDG.128 (twin warp re-loads -> L1 hit).
// Syncs: one at entry (act ready), one after the k-loop (act reads done).
// EPI: 0 = relu->act; 1 = relu->act + density partials; 2 = rgb partials only
template<int NB, int EPI>
__device__ __noinline__ void layer(char* smem, uint32_t smb, unsigned img_u4,
                                   const float* __restrict__ bias_g,
                                   const float* __restrict__ head_g,
                                   int nc, int xc) {
    const int tid  = threadIdx.x;
    const int lane = tid & 31;
    const int w    = tid >> 5;
    const int NT   = NB * 4;          // n8-tiles total (4 n-groups)
    const int wm   = w & 1;
    const int wn   = w >> 1;
    const int mb   = wm * 32;
    const int nb   = wn * (NB * 8);   // first n column of this warp

    float acc[2][NB][4];
#pragma unroll
    for (int i = 0; i < 2; ++i)
#pragma unroll
        for (int j = 0; j < NB; ++j)
#pragma unroll
            for (int r = 0; r < 4; ++r) acc[i][j][r] = 0.0f;

    __syncthreads();                  // prev layer's act writes visible

    const int m_off  = (lane & 7) + ((lane >> 3) & 1) * 8;
    const int ak_off = (lane >> 4) * 8;

#pragma unroll 1
    for (int c = 0; c < nc; ++c) {
        uint4 F[NB];
        const uint4* fb = g_wf + img_u4 + (unsigned)(c * NT + wn * NB) * 32u + lane;
#pragma unroll
        for (int jp = 0; jp < NB; ++jp) F[jp] = __ldg(fb + jp * 32);

        uint32_t ab; int astr, koff;
        if (c < xc) { ab = smb + SM_ACT; astr = 264; koff = c * 32; }
        else        { ab = smb + SM_EMB; astr = 72;  koff = (c - xc) * 32; }

#pragma unroll
        for (int ks = 0; ks < 2; ++ks) {
            int kk = koff + ks * 16;
            uint32_t A[2][4];
#pragma unroll
            for (int i = 0; i < 2; ++i)
                ldsm4(A[i], ab + ((mb + i * 16 + m_off) * astr + kk + ak_off) * 2);
#pragma unroll
            for (int jp = 0; jp < NB; ++jp) {
                uint32_t bb[2];
                bb[0] = ks ? F[jp].z : F[jp].x;
                bb[1] = ks ? F[jp].w : F[jp].y;
#pragma unroll
                for (int i = 0; i < 2; ++i)
                    mma_f16(acc[i][jp], A[i], bb);
            }
        }
    }
    __syncthreads();                  // all act reads done before writeback

    // ---- epilogue ----
    float ds[4];
    float pr[12];
    if (EPI == 1) {
#pragma unroll
        for (int q = 0; q < 4; ++q) ds[q] = 0.0f;
    }
    if (EPI == 2) {
#pragma unroll
        for (int q = 0; q < 12; ++q) pr[q] = 0.0f;
    }
    const int nb0 = nb + (lane & 3) * 2;
#pragma unroll
    for (int j = 0; j < NB; ++j) {
        int n = nb0 + j * 8;
        float2 b2 = __ldg(reinterpret_cast<const float2*>(bias_g + n));
        float2 wd2;
        float2 wr2[3];
        if (EPI == 1) wd2 = __ldg(reinterpret_cast<const float2*>(head_g + n));
        if (EPI == 2) {
#pragma unroll
            for (int ch = 0; ch < 3; ++ch)
                wr2[ch] = __ldg(reinterpret_cast<const float2*>(head_g + ch * 128 + n));
        }
#pragma unroll
        for (int i = 0; i < 2; ++i) {
            float r00 = fmaxf(acc[i][j][0] + b2.x, 0.0f);
            float r01 = fmaxf(acc[i][j][1] + b2.y, 0.0f);
            float r10 = fmaxf(acc[i][j][2] + b2.x, 0.0f);
            float r11 = fmaxf(acc[i][j][3] + b2.y, 0.0f);
            if (EPI != 2) {
                int m0 = mb + i * 16 + (lane >> 2);
                *(uint32_t*)(smem + SM_ACT + (m0 * 264 + n) * 2)       = packh(r00, r01);
                *(uint32_t*)(smem + SM_ACT + ((m0 + 8) * 264 + n) * 2) = packh(r10, r11);
            }
            if (EPI == 1) {
                ds[i * 2 + 0] += r00 * wd2.x + r01 * wd2.y;
                ds[i * 2 + 1] += r10 * wd2.x + r11 * wd2.y;
            }
            if (EPI == 2) {
#pragma unroll
                for (int ch = 0; ch < 3; ++ch) {
                    pr[(i * 2 + 0) * 3 + ch] += r00 * wr2[ch].x + r01 * wr2[ch].y;
                    pr[(i * 2 + 1) * 3 + ch] += r10 * wr2[ch].x + r11 * wr2[ch].y;
                }
            }
        }
    }
    if (EPI == 1) {
#pragma unroll
        for (int q = 0; q < 4; ++q) {
            ds[q] += __shfl_xor_sync(0xffffffffu, ds[q], 1);
            ds[q] += __shfl_xor_sync(0xffffffffu, ds[q], 2);
        }
        if ((lane & 3) == 0) {
            float* dp = (float*)(smem + SM_DENSP);
#pragma unroll
            for (int i = 0; i < 2; ++i)
#pragma unroll
            for (int h2 = 0; h2 < 2; ++h2)
                dp[wn * 64 + mb + i * 16 + h2 * 8 + (lane >> 2)] = ds[i * 2 + h2];
        }
    }
    if (EPI == 2) {
#pragma unroll
        for (int q = 0; q < 12; ++q) {
            pr[q] += __shfl_xor_sync(0xffffffffu, pr[q], 1);
            pr[q] += __shfl_xor_sync(0xffffffffu, pr[q], 2);
        }
        if ((lane & 3) == 0) {
            float* rp = (float*)(smem + SM_RGBP);
#pragma unroll
            for (int i = 0; i < 2; ++i)
#pragma unroll
            for (int h2 = 0; h2 < 2; ++h2)
#pragma unroll
            for (int ch = 0; ch < 3; ++ch)
                rp[(ch * 4 + wn) * 64 + mb + i * 16 + h2 * 8 + (lane >> 2)]
                    = pr[(i * 2 + h2) * 3 + ch];
        }
    }
}

// ---------------- main fused kernel ----------------
__global__ void __launch_bounds__(THREADS, 2) nerf_hmma(
    const float* __restrict__ sp,   const float* __restrict__ dirs,
    const float* __restrict__ bx0,  const float* __restrict__ bx1,
    const float* __restrict__ bx2,  const float* __restrict__ bx3,
    const float* __restrict__ bx4,  const float* __restrict__ bx5,
    const float* __restrict__ bx6,  const float* __restrict__ bx7,
    const float* __restrict__ bd0,  const float* __restrict__ bden,
    const float* __restrict__ bfeat,const float* __restrict__ brgb,
    const float* __restrict__ Wden, const float* __restrict__ Wrgb,
    float* __restrict__ out)
{
    extern __shared__ char smem[];
    uint32_t smb = s2u(smem);
    const int tid = threadIdx.x;
    const int p0  = blockIdx.x * NSAMP;

    // xyz harmonic embedding -> fp16 tile [64][72] (cols 0-63 data, col 63 zero)
    if (tid < NSAMP) {
        float e[64];
        const float* pp = sp + (size_t)(p0 + tid) * 3;
#pragma unroll
        for (int d = 0; d < 3; ++d) {
            float x = pp[d], f = 1.0f;
#pragma unroll
            for (int h = 0; h < 10; ++h) {
                float s, c;
                sincosf(x * f, &s, &c);
                e[d * 10 + h] = s;
                e[30 + d * 10 + h] = c;
                f *= 2.0f;
            }
            e[60 + d] = x;
        }
        e[63] = 0.0f;
#pragma unroll
        for (int k = 0; k < 32; ++k)
            *(uint32_t*)(smem + SM_EMB + (tid * 72 + k * 2) * 2) = packh(e[2 * k], e[2 * k + 1]);
    }
    // each layer begins with __syncthreads(): emb visible before first reads

    layer<8, 0>(smem, smb, IOFF_L0 / 8u, bx0, 0,  2,  0);
    layer<8, 0>(smem, smb, IOFF_L1 / 8u, bx1, 0,  8,  8);
    layer<8, 0>(smem, smb, IOFF_L2 / 8u, bx2, 0,  8,  8);
    layer<8, 0>(smem, smb, IOFF_L3 / 8u, bx3, 0,  8,  8);
    layer<8, 0>(smem, smb, IOFF_L4 / 8u, bx4, 0, 10,  8);   // skip concat
    layer<8, 0>(smem, smb, IOFF_L5 / 8u, bx5, 0,  8,  8);
    layer<8, 0>(smem, smb, IOFF_L6 / 8u, bx6, 0,  8,  8);
    layer<8, 1>(smem, smb, IOFF_L7 / 8u, bx7, Wden, 8, 8);  // + density partials

    __syncthreads();
    if (tid < NSAMP) {
        const float* dp = (const float*)(smem + SM_DENSP);
        float s = __ldg(bden);
#pragma unroll
        for (int q = 0; q < 4; ++q) s += dp[q * 64 + tid];
        ((float*)(smem + SM_DENS))[tid] = fmaxf(s, 0.0f);
    }

    layer<8, 0>(smem, smb, IOFF_FT / 8u, bfeat, 0, 8, 8);

    // direction embedding: 1 ray per CTA -> scratch[32] -> [64][72] tile cols 0-63 (27 data + zeros)
    if (tid < 32) {
        float v = 0.0f;
        if (tid < 12) {
            float x = __ldg(dirs + (size_t)blockIdx.x * 3 + (tid >> 2));
            v = sinf(x * (float)(1 << (tid & 3)));
        } else if (tid < 24) {
            int q = tid - 12;
            float x = __ldg(dirs + (size_t)blockIdx.x * 3 + (q >> 2));
            v = cosf(x * (float)(1 << (q & 3)));
        } else if (tid < 27) {
            v = __ldg(dirs + (size_t)blockIdx.x * 3 + (tid - 24));
        }
        ((float*)(smem + SM_DIRS))[tid] = v;
    }
    __syncthreads();
#pragma unroll 1
    for (int idx = tid; idx < NSAMP * 32; idx += THREADS) {
        int row = idx >> 5, k2 = idx & 31;       // k2 = uint32 index (2 cols each)
        uint32_t v = 0u;
        if (k2 < 16) {
            const float* sc = (const float*)(smem + SM_DIRS);
            v = packh(sc[2 * k2], sc[2 * k2 + 1]);
        }
        *(uint32_t*)(smem + SM_EMB + (row * 72 + k2 * 2) * 2) = v;
    }
    // dir layer's entry sync makes these writes visible

    layer<4, 2>(smem, smb, IOFF_DIR / 8u, bd0, Wrgb, 10, 8);   // rgb partials

    __syncthreads();
    if (tid < NSAMP) {
        const float* rp = (const float*)(smem + SM_RGBP);
        float* op = out + (size_t)(p0 + tid) * 4;
        op[0] = ((const float*)(smem + SM_DENS))[tid];
#pragma unroll
        for (int ch = 0; ch < 3; ++ch) {
            float s = __ldg(brgb + ch);
#pragma unroll
            for (int q = 0; q < 4; ++q) s += rp[(ch * 4 + q) * 64 + tid];
            op[1 + ch] = 1.0f / (1.0f + expf(-s));
        }
    }
}

extern "C" void kernel_launch(void* const* d_in, const int* in_sizes, int n_in,
                              void* d_out, int out_size) {
    (void)in_sizes; (void)n_in; (void)out_size;
    prep_all<<<(IMG_ELEMS / 2 + 255) / 256, 256>>>(
        (const float*)d_in[2],  (const float*)d_in[4],
        (const float*)d_in[6],  (const float*)d_in[8],
        (const float*)d_in[10], (const float*)d_in[12],
        (const float*)d_in[14], (const float*)d_in[16],
        (const float*)d_in[22],   // Wfeat
        (const float*)d_in[18]);  // Wd0

    cudaFuncSetAttribute(nerf_hmma, cudaFuncAttributeMaxDynamicSharedMemorySize, SMEM_BYTES);
    nerf_hmma<<<GRID, THREADS, SMEM_BYTES>>>(
        (const float*)d_in[0],  (const float*)d_in[1],
        (const float*)d_in[3],  (const float*)d_in[5],
        (const float*)d_in[7],  (const float*)d_in[9],
        (const float*)d_in[11], (const float*)d_in[13],
        (const float*)d_in[15], (const float*)d_in[17],
        (const float*)d_in[19], (const float*)d_in[21],
        (const float*)d_in[23], (const float*)d_in[25],
        (const float*)d_in[20],   // Wden
        (const float*)d_in[24],   // Wrgb
        (float*)d_out);
}